// round 14
// baseline (speedup 1.0000x reference)
#include <cuda_runtime.h>
#include <cuda_bf16.h>
#include <float.h>
#include <stdint.h>

#define DIM     300
#define DIM4    75            // float4 per row
#define ROWB    (DIM * 4)     // 1200 bytes per row
#define MAXK    16
#define TPB     512           // 16 warps
#define WPB     (TPB / 32)
#define NB      296           // 2 blocks per SM -> 32 warps/SM
#define AHEAD   2             // prefetch lead in quad-iterations (4.8KB each)
                              // L2 lead footprint: 2*4.8KB*16w*296b ~= 45MB

// Scratch (allocation-free rule: __device__ globals)
__device__ float        g_cand_v[NB * MAXK];
__device__ int          g_cand_i[NB * MAXK];
__device__ unsigned int g_done = 0;

// ---------------------------------------------------------------------------
// PTX helpers
// ---------------------------------------------------------------------------
// Bulk prefetch into L2 via the TMA engine — fire-and-forget, no mbarrier,
// no LSU/MSHR tracking on the SM side.
__device__ __forceinline__ void bulk_prefetch_l2(const void* src, unsigned bytes)
{
    asm volatile("cp.async.bulk.prefetch.L2.global [%0], %1;"
                 :: "l"(src), "r"(bytes) : "memory");
}

// ---------------------------------------------------------------------------
// top-K helpers (ascending-sorted register list; slot 0 = current min)
// ---------------------------------------------------------------------------
__device__ __forceinline__ void topk_insert(float* vals, int* ids, int K,
                                            float s, int id)
{
    if (s > vals[0] || (s == vals[0] && id < ids[0])) {
        int j = 0;
        while (j < K - 1 &&
               (s > vals[j + 1] || (s == vals[j + 1] && id < ids[j + 1]))) {
            vals[j] = vals[j + 1];
            ids [j] = ids [j + 1];
            j++;
        }
        vals[j] = s;
        ids [j] = id;
    }
}

#define WARP_EXTRACT_TOPK(vals, ids, K, EMIT)                                  \
    do {                                                                       \
        int ptr = (K) - 1;                                                     \
        for (int r = 0; r < (K); r++) {                                        \
            float v  = (ptr >= 0) ? (vals)[ptr] : -FLT_MAX;                    \
            int   id = (ptr >= 0) ? (ids)[ptr]  : 0x7fffffff;                  \
            float bv = v; int bid = id; int bl = lane;                         \
            _Pragma("unroll")                                                  \
            for (int off = 16; off; off >>= 1) {                               \
                float ov  = __shfl_xor_sync(0xffffffffu, bv,  off);            \
                int   oid = __shfl_xor_sync(0xffffffffu, bid, off);            \
                int   ol  = __shfl_xor_sync(0xffffffffu, bl,  off);            \
                if (ov > bv || (ov == bv && oid < bid)) {                      \
                    bv = ov; bid = oid; bl = ol;                               \
                }                                                              \
            }                                                                  \
            if (lane == bl) ptr--;                                             \
            if (lane == 0) { EMIT; }                                           \
        }                                                                      \
    } while (0)

__device__ __forceinline__ float dot_row(const float4* __restrict__ rp,
                                         int lane,
                                         float4 b0, float4 b1, float4 b2)
{
    float4 a0 = rp[lane];
    float4 a1 = rp[lane + 32];
    float acc = a0.x * b0.x + a0.y * b0.y + a0.z * b0.z + a0.w * b0.w
              + a1.x * b1.x + a1.y * b1.y + a1.z * b1.z + a1.w * b1.w;
    if (lane < DIM4 - 64) {
        float4 a2 = rp[lane + 64];
        acc += a2.x * b2.x + a2.y * b2.y + a2.z * b2.z + a2.w * b2.w;
    }
    return acc;
}
__device__ __forceinline__ float warp_sum(float acc)
{
#pragma unroll
    for (int off = 16; off; off >>= 1)
        acc += __shfl_xor_sync(0xffffffffu, acc, off);
    return acc;
}

// 4 adjacent rows: 12 independent LDG.128 in flight, then 4 interleaved
// butterfly reduction chains.
__device__ __forceinline__ void dot4(const float4* __restrict__ r0p,
                                     const float4* __restrict__ r1p,
                                     const float4* __restrict__ r2p,
                                     const float4* __restrict__ r3p,
                                     int lane, float4 b0, float4 b1, float4 b2,
                                     float& s0, float& s1, float& s2, float& s3)
{
    float4 a0 = r0p[lane],      a1 = r1p[lane],      a2 = r2p[lane],      a3 = r3p[lane];
    float4 c0 = r0p[lane + 32], c1 = r1p[lane + 32], c2 = r2p[lane + 32], c3 = r3p[lane + 32];

    s0 = a0.x*b0.x + a0.y*b0.y + a0.z*b0.z + a0.w*b0.w
       + c0.x*b1.x + c0.y*b1.y + c0.z*b1.z + c0.w*b1.w;
    s1 = a1.x*b0.x + a1.y*b0.y + a1.z*b0.z + a1.w*b0.w
       + c1.x*b1.x + c1.y*b1.y + c1.z*b1.z + c1.w*b1.w;
    s2 = a2.x*b0.x + a2.y*b0.y + a2.z*b0.z + a2.w*b0.w
       + c2.x*b1.x + c2.y*b1.y + c2.z*b1.z + c2.w*b1.w;
    s3 = a3.x*b0.x + a3.y*b0.y + a3.z*b0.z + a3.w*b0.w
       + c3.x*b1.x + c3.y*b1.y + c3.z*b1.z + c3.w*b1.w;

    if (lane < DIM4 - 64) {
        float4 d0 = r0p[lane + 64], d1 = r1p[lane + 64];
        float4 d2 = r2p[lane + 64], d3 = r3p[lane + 64];
        s0 += d0.x*b2.x + d0.y*b2.y + d0.z*b2.z + d0.w*b2.w;
        s1 += d1.x*b2.x + d1.y*b2.y + d1.z*b2.z + d1.w*b2.w;
        s2 += d2.x*b2.x + d2.y*b2.y + d2.z*b2.z + d2.w*b2.w;
        s3 += d3.x*b2.x + d3.y*b2.y + d3.z*b2.z + d3.w*b2.w;
    }
#pragma unroll
    for (int off = 16; off; off >>= 1) {
        s0 += __shfl_xor_sync(0xffffffffu, s0, off);
        s1 += __shfl_xor_sync(0xffffffffu, s1, off);
        s2 += __shfl_xor_sync(0xffffffffu, s2, off);
        s3 += __shfl_xor_sync(0xffffffffu, s3, off);
    }
}

// ---------------------------------------------------------------------------
// Fused persistent kernel: 4-row LDG demand + TMA bulk-prefetch-to-L2 pacing
// + hierarchical top-K.  No smem ring, no mbarriers, no loop barriers.
// ---------------------------------------------------------------------------
__global__ void __launch_bounds__(TPB, 2)
fused_sim_topk_kernel(const int* __restrict__ wordid,
                      const float* __restrict__ emb,
                      float* __restrict__ out,
                      int V, int K)
{
    __shared__ float4 swv[DIM4];
    __shared__ float  sv[WPB * MAXK];
    __shared__ int    si[WPB * MAXK];
    __shared__ int    s_last;

    const int tid  = threadIdx.x;
    const int lane = tid & 31;
    const int warp = tid >> 5;

    {
        int w = wordid[0];
        if (tid < DIM4)
            swv[tid] = reinterpret_cast<const float4*>(emb + (size_t)w * DIM)[tid];
    }
    __syncthreads();

    const float4 b0 = swv[lane];
    const float4 b1 = swv[lane + 32];
    const float4 b2 = (lane < DIM4 - 64) ? swv[lane + 64]
                                         : make_float4(0.f, 0.f, 0.f, 0.f);

    // --- this block's contiguous row chunk ---
    const int chunk    = (V + NB - 1) / NB;
    const int row_base = blockIdx.x * chunk;
    int rows_blk = V - row_base;
    if (rows_blk > chunk) rows_blk = chunk;
    if (rows_blk < 0)     rows_blk = 0;
    const int row_end = row_base + rows_blk;
    const int nquads  = rows_blk / 4;             // adjacent 4-row groups

    const float4* emb4  = reinterpret_cast<const float4*>(emb);
    const char*   embc  = reinterpret_cast<const char*>(emb);

    // --- per-warp running top-K (lane 0 holds it) ---
    float vals[MAXK];
    int   ids [MAXK];
#pragma unroll
    for (int j = 0; j < MAXK; j++) { vals[j] = -FLT_MAX; ids[j] = 0x7fffffff; }

    // --- prologue: each warp bulk-prefetches its first AHEAD iterations ---
    if (lane == 0) {
#pragma unroll
        for (int k = 0; k < AHEAD; k++) {
            int q = warp + k * WPB;
            if (q < nquads) {
                int r = row_base + 4 * q;
                bulk_prefetch_l2(embc + (size_t)r * ROWB, 4 * ROWB);
            }
        }
    }

    // --- main loop: warp-strided over 4-row groups ---
    for (int q = warp; q < nquads; q += WPB) {
        // self-prefetch the group AHEAD iterations ahead (TMA engine, no MSHR)
        if (lane == 0) {
            int qq = q + AHEAD * WPB;
            if (qq < nquads) {
                int pr = row_base + 4 * qq;
                bulk_prefetch_l2(embc + (size_t)pr * ROWB, 4 * ROWB);
            }
        }

        const int r0 = row_base + 4 * q;
        float s0, s1, s2, s3;
        dot4(emb4 + (size_t)r0 * DIM4,       emb4 + (size_t)(r0 + 1) * DIM4,
             emb4 + (size_t)(r0 + 2) * DIM4, emb4 + (size_t)(r0 + 3) * DIM4,
             lane, b0, b1, b2, s0, s1, s2, s3);
        if (lane == 0) {
            topk_insert(vals, ids, K, s0, r0);
            topk_insert(vals, ids, K, s1, r0 + 1);
            topk_insert(vals, ids, K, s2, r0 + 2);
            topk_insert(vals, ids, K, s3, r0 + 3);
        }
    }

    // --- tail rows (< 4), one per warp ---
    for (int r = row_base + 4 * nquads + warp; r < row_end; r += WPB) {
        float acc = warp_sum(dot_row(emb4 + (size_t)r * DIM4, lane, b0, b1, b2));
        if (lane == 0) topk_insert(vals, ids, K, acc, r);
    }

    // --- phase 2: block merge -> per-block candidates in gmem ---
    if (lane == 0) {
#pragma unroll
        for (int j = 0; j < MAXK; j++) {
            if (j < K) { sv[warp * K + j] = vals[j]; si[warp * K + j] = ids[j]; }
        }
    }
    __syncthreads();

    if (warp == 0) {
        float v2[MAXK];
        int   i2[MAXK];
#pragma unroll
        for (int j = 0; j < MAXK; j++) { v2[j] = -FLT_MAX; i2[j] = 0x7fffffff; }
        for (int e = lane; e < WPB * K; e += 32)
            topk_insert(v2, i2, K, sv[e], si[e]);

        float* gv = g_cand_v + (size_t)blockIdx.x * K;
        int*   gi = g_cand_i + (size_t)blockIdx.x * K;
        WARP_EXTRACT_TOPK(v2, i2, K, { gv[r] = bv; gi[r] = bid; });
    }

    // --- phase 3: last block to finish does the final merge ---
    __threadfence();
    if (tid == 0) {
        unsigned int prev = atomicAdd(&g_done, 1u);
        s_last = (prev == gridDim.x - 1) ? 1 : 0;
    }
    __syncthreads();
    if (!s_last) return;

    {
        const int NC = gridDim.x * K;
        float v3[MAXK];
        int   i3[MAXK];
#pragma unroll
        for (int j = 0; j < MAXK; j++) { v3[j] = -FLT_MAX; i3[j] = 0x7fffffff; }
        for (int e = tid; e < NC; e += TPB)
            topk_insert(v3, i3, K, g_cand_v[e], g_cand_i[e]);

        WARP_EXTRACT_TOPK(v3, i3, K, { sv[warp * K + r] = bv; si[warp * K + r] = bid; });
        __syncthreads();

        if (warp == 0) {
            float v4[MAXK];
            int   i4[MAXK];
#pragma unroll
            for (int j = 0; j < MAXK; j++) { v4[j] = -FLT_MAX; i4[j] = 0x7fffffff; }
            for (int e = lane; e < WPB * K; e += 32)
                topk_insert(v4, i4, K, sv[e], si[e]);

            WARP_EXTRACT_TOPK(v4, i4, K, {
                out[r]     = bv;
                out[K + r] = (float)bid;
            });
        }

        __syncthreads();
        if (tid == 0) g_done = 0;   // reset for deterministic graph replay
    }
}

// ---------------------------------------------------------------------------
// kernel_launch — single fused persistent kernel (2 CTAs per SM).
// Inputs: wordid int32 [1], embedding float32 [V*300], topk int32 [1].
// Output: float32 [2K]: K values then K indices (K = topk+1 = out_size/2).
// ---------------------------------------------------------------------------
extern "C" void kernel_launch(void* const* d_in, const int* in_sizes, int n_in,
                              void* d_out, int out_size)
{
    const int*   wordid = (const int*)d_in[0];
    const float* emb    = (const float*)d_in[1];

    int V = in_sizes[1] / DIM;       // 200000
    int K = out_size / 2;            // 11
    if (K > MAXK) K = MAXK;

    fused_sim_topk_kernel<<<NB, TPB>>>(wordid, emb, (float*)d_out, V, K);
}

// round 15
// speedup vs baseline: 1.0208x; 1.0208x over previous
#include <cuda_runtime.h>
#include <cuda_bf16.h>
#include <float.h>
#include <stdint.h>

#define DIM     300
#define DIM4    75            // float4 per row
#define ROWB    (DIM * 4)     // 1200 bytes per row
#define MAXK    16
#define TPB     512           // 16 warps
#define WPB     (TPB / 32)
#define NB      296           // 2 blocks per SM -> 32 warps/SM
#define AHEAD   2             // prefetch lead in quad-iterations (4.8KB each)
                              // L2 lead footprint: 2*4.8KB*16w*296b ~= 45MB

// Scratch (allocation-free rule: __device__ globals)
__device__ float        g_cand_v[NB * MAXK];
__device__ int          g_cand_i[NB * MAXK];
__device__ unsigned int g_done = 0;

// ---------------------------------------------------------------------------
// PTX helpers
// ---------------------------------------------------------------------------
// Bulk prefetch into L2 via the TMA engine — fire-and-forget, no mbarrier,
// no LSU/MSHR tracking on the SM side.
__device__ __forceinline__ void bulk_prefetch_l2(const void* src, unsigned bytes)
{
    asm volatile("cp.async.bulk.prefetch.L2.global [%0], %1;"
                 :: "l"(src), "r"(bytes) : "memory");
}

// ---------------------------------------------------------------------------
// top-K helpers (ascending-sorted register list; slot 0 = current min)
// ---------------------------------------------------------------------------
__device__ __forceinline__ void topk_insert(float* vals, int* ids, int K,
                                            float s, int id)
{
    if (s > vals[0] || (s == vals[0] && id < ids[0])) {
        int j = 0;
        while (j < K - 1 &&
               (s > vals[j + 1] || (s == vals[j + 1] && id < ids[j + 1]))) {
            vals[j] = vals[j + 1];
            ids [j] = ids [j + 1];
            j++;
        }
        vals[j] = s;
        ids [j] = id;
    }
}

#define WARP_EXTRACT_TOPK(vals, ids, K, EMIT)                                  \
    do {                                                                       \
        int ptr = (K) - 1;                                                     \
        for (int r = 0; r < (K); r++) {                                        \
            float v  = (ptr >= 0) ? (vals)[ptr] : -FLT_MAX;                    \
            int   id = (ptr >= 0) ? (ids)[ptr]  : 0x7fffffff;                  \
            float bv = v; int bid = id; int bl = lane;                         \
            _Pragma("unroll")                                                  \
            for (int off = 16; off; off >>= 1) {                               \
                float ov  = __shfl_xor_sync(0xffffffffu, bv,  off);            \
                int   oid = __shfl_xor_sync(0xffffffffu, bid, off);            \
                int   ol  = __shfl_xor_sync(0xffffffffu, bl,  off);            \
                if (ov > bv || (ov == bv && oid < bid)) {                      \
                    bv = ov; bid = oid; bl = ol;                               \
                }                                                              \
            }                                                                  \
            if (lane == bl) ptr--;                                             \
            if (lane == 0) { EMIT; }                                           \
        }                                                                      \
    } while (0)

__device__ __forceinline__ float dot_row(const float4* __restrict__ rp,
                                         int lane,
                                         float4 b0, float4 b1, float4 b2)
{
    float4 a0 = rp[lane];
    float4 a1 = rp[lane + 32];
    float acc = a0.x * b0.x + a0.y * b0.y + a0.z * b0.z + a0.w * b0.w
              + a1.x * b1.x + a1.y * b1.y + a1.z * b1.z + a1.w * b1.w;
    if (lane < DIM4 - 64) {
        float4 a2 = rp[lane + 64];
        acc += a2.x * b2.x + a2.y * b2.y + a2.z * b2.z + a2.w * b2.w;
    }
    return acc;
}
__device__ __forceinline__ float warp_sum(float acc)
{
#pragma unroll
    for (int off = 16; off; off >>= 1)
        acc += __shfl_xor_sync(0xffffffffu, acc, off);
    return acc;
}

// 4 adjacent rows: 12 independent LDG.128 in flight, then 4 interleaved
// butterfly reduction chains.
__device__ __forceinline__ void dot4(const float4* __restrict__ r0p,
                                     const float4* __restrict__ r1p,
                                     const float4* __restrict__ r2p,
                                     const float4* __restrict__ r3p,
                                     int lane, float4 b0, float4 b1, float4 b2,
                                     float& s0, float& s1, float& s2, float& s3)
{
    float4 a0 = r0p[lane],      a1 = r1p[lane],      a2 = r2p[lane],      a3 = r3p[lane];
    float4 c0 = r0p[lane + 32], c1 = r1p[lane + 32], c2 = r2p[lane + 32], c3 = r3p[lane + 32];

    s0 = a0.x*b0.x + a0.y*b0.y + a0.z*b0.z + a0.w*b0.w
       + c0.x*b1.x + c0.y*b1.y + c0.z*b1.z + c0.w*b1.w;
    s1 = a1.x*b0.x + a1.y*b0.y + a1.z*b0.z + a1.w*b0.w
       + c1.x*b1.x + c1.y*b1.y + c1.z*b1.z + c1.w*b1.w;
    s2 = a2.x*b0.x + a2.y*b0.y + a2.z*b0.z + a2.w*b0.w
       + c2.x*b1.x + c2.y*b1.y + c2.z*b1.z + c2.w*b1.w;
    s3 = a3.x*b0.x + a3.y*b0.y + a3.z*b0.z + a3.w*b0.w
       + c3.x*b1.x + c3.y*b1.y + c3.z*b1.z + c3.w*b1.w;

    if (lane < DIM4 - 64) {
        float4 d0 = r0p[lane + 64], d1 = r1p[lane + 64];
        float4 d2 = r2p[lane + 64], d3 = r3p[lane + 64];
        s0 += d0.x*b2.x + d0.y*b2.y + d0.z*b2.z + d0.w*b2.w;
        s1 += d1.x*b2.x + d1.y*b2.y + d1.z*b2.z + d1.w*b2.w;
        s2 += d2.x*b2.x + d2.y*b2.y + d2.z*b2.z + d2.w*b2.w;
        s3 += d3.x*b2.x + d3.y*b2.y + d3.z*b2.z + d3.w*b2.w;
    }
#pragma unroll
    for (int off = 16; off; off >>= 1) {
        s0 += __shfl_xor_sync(0xffffffffu, s0, off);
        s1 += __shfl_xor_sync(0xffffffffu, s1, off);
        s2 += __shfl_xor_sync(0xffffffffu, s2, off);
        s3 += __shfl_xor_sync(0xffffffffu, s3, off);
    }
}

// ---------------------------------------------------------------------------
// Fused persistent kernel: 4-row LDG demand + TMA bulk-prefetch-to-L2 pacing
// + hierarchical top-K.  No smem ring, no mbarriers, no loop barriers.
// ---------------------------------------------------------------------------
__global__ void __launch_bounds__(TPB, 2)
fused_sim_topk_kernel(const int* __restrict__ wordid,
                      const float* __restrict__ emb,
                      float* __restrict__ out,
                      int V, int K)
{
    __shared__ float4 swv[DIM4];
    __shared__ float  sv[WPB * MAXK];
    __shared__ int    si[WPB * MAXK];
    __shared__ int    s_last;

    const int tid  = threadIdx.x;
    const int lane = tid & 31;
    const int warp = tid >> 5;

    {
        int w = wordid[0];
        if (tid < DIM4)
            swv[tid] = reinterpret_cast<const float4*>(emb + (size_t)w * DIM)[tid];
    }
    __syncthreads();

    const float4 b0 = swv[lane];
    const float4 b1 = swv[lane + 32];
    const float4 b2 = (lane < DIM4 - 64) ? swv[lane + 64]
                                         : make_float4(0.f, 0.f, 0.f, 0.f);

    // --- this block's contiguous row chunk ---
    const int chunk    = (V + NB - 1) / NB;
    const int row_base = blockIdx.x * chunk;
    int rows_blk = V - row_base;
    if (rows_blk > chunk) rows_blk = chunk;
    if (rows_blk < 0)     rows_blk = 0;
    const int row_end = row_base + rows_blk;
    const int nquads  = rows_blk / 4;             // adjacent 4-row groups

    const float4* emb4  = reinterpret_cast<const float4*>(emb);
    const char*   embc  = reinterpret_cast<const char*>(emb);

    // --- per-warp running top-K (lane 0 holds it) ---
    float vals[MAXK];
    int   ids [MAXK];
#pragma unroll
    for (int j = 0; j < MAXK; j++) { vals[j] = -FLT_MAX; ids[j] = 0x7fffffff; }

    // --- prologue: each warp bulk-prefetches its first AHEAD iterations ---
    if (lane == 0) {
#pragma unroll
        for (int k = 0; k < AHEAD; k++) {
            int q = warp + k * WPB;
            if (q < nquads) {
                int r = row_base + 4 * q;
                bulk_prefetch_l2(embc + (size_t)r * ROWB, 4 * ROWB);
            }
        }
    }

    // --- main loop: warp-strided over 4-row groups ---
    for (int q = warp; q < nquads; q += WPB) {
        // self-prefetch the group AHEAD iterations ahead (TMA engine, no MSHR)
        if (lane == 0) {
            int qq = q + AHEAD * WPB;
            if (qq < nquads) {
                int pr = row_base + 4 * qq;
                bulk_prefetch_l2(embc + (size_t)pr * ROWB, 4 * ROWB);
            }
        }

        const int r0 = row_base + 4 * q;
        float s0, s1, s2, s3;
        dot4(emb4 + (size_t)r0 * DIM4,       emb4 + (size_t)(r0 + 1) * DIM4,
             emb4 + (size_t)(r0 + 2) * DIM4, emb4 + (size_t)(r0 + 3) * DIM4,
             lane, b0, b1, b2, s0, s1, s2, s3);
        if (lane == 0) {
            topk_insert(vals, ids, K, s0, r0);
            topk_insert(vals, ids, K, s1, r0 + 1);
            topk_insert(vals, ids, K, s2, r0 + 2);
            topk_insert(vals, ids, K, s3, r0 + 3);
        }
    }

    // --- tail rows (< 4), one per warp ---
    for (int r = row_base + 4 * nquads + warp; r < row_end; r += WPB) {
        float acc = warp_sum(dot_row(emb4 + (size_t)r * DIM4, lane, b0, b1, b2));
        if (lane == 0) topk_insert(vals, ids, K, acc, r);
    }

    // --- phase 2: block merge -> per-block candidates in gmem ---
    if (lane == 0) {
#pragma unroll
        for (int j = 0; j < MAXK; j++) {
            if (j < K) { sv[warp * K + j] = vals[j]; si[warp * K + j] = ids[j]; }
        }
    }
    __syncthreads();

    if (warp == 0) {
        float v2[MAXK];
        int   i2[MAXK];
#pragma unroll
        for (int j = 0; j < MAXK; j++) { v2[j] = -FLT_MAX; i2[j] = 0x7fffffff; }
        for (int e = lane; e < WPB * K; e += 32)
            topk_insert(v2, i2, K, sv[e], si[e]);

        float* gv = g_cand_v + (size_t)blockIdx.x * K;
        int*   gi = g_cand_i + (size_t)blockIdx.x * K;
        WARP_EXTRACT_TOPK(v2, i2, K, { gv[r] = bv; gi[r] = bid; });
    }

    // --- phase 3: last block to finish does the final merge ---
    __threadfence();
    if (tid == 0) {
        unsigned int prev = atomicAdd(&g_done, 1u);
        s_last = (prev == gridDim.x - 1) ? 1 : 0;
    }
    __syncthreads();
    if (!s_last) return;

    {
        const int NC = gridDim.x * K;
        float v3[MAXK];
        int   i3[MAXK];
#pragma unroll
        for (int j = 0; j < MAXK; j++) { v3[j] = -FLT_MAX; i3[j] = 0x7fffffff; }
        for (int e = tid; e < NC; e += TPB)
            topk_insert(v3, i3, K, g_cand_v[e], g_cand_i[e]);

        WARP_EXTRACT_TOPK(v3, i3, K, { sv[warp * K + r] = bv; si[warp * K + r] = bid; });
        __syncthreads();

        if (warp == 0) {
            float v4[MAXK];
            int   i4[MAXK];
#pragma unroll
            for (int j = 0; j < MAXK; j++) { v4[j] = -FLT_MAX; i4[j] = 0x7fffffff; }
            for (int e = lane; e < WPB * K; e += 32)
                topk_insert(v4, i4, K, sv[e], si[e]);

            WARP_EXTRACT_TOPK(v4, i4, K, {
                out[r]     = bv;
                out[K + r] = (float)bid;
            });
        }

        __syncthreads();
        if (tid == 0) g_done = 0;   // reset for deterministic graph replay
    }
}

// ---------------------------------------------------------------------------
// kernel_launch — single fused persistent kernel (2 CTAs per SM).
// Inputs: wordid int32 [1], embedding float32 [V*300], topk int32 [1].
// Output: float32 [2K]: K values then K indices (K = topk+1 = out_size/2).
// ---------------------------------------------------------------------------
extern "C" void kernel_launch(void* const* d_in, const int* in_sizes, int n_in,
                              void* d_out, int out_size)
{
    const int*   wordid = (const int*)d_in[0];
    const float* emb    = (const float*)d_in[1];

    int V = in_sizes[1] / DIM;       // 200000
    int K = out_size / 2;            // 11
    if (K > MAXK) K = MAXK;

    fused_sim_topk_kernel<<<NB, TPB>>>(wordid, emb, (float*)d_out, V, K);
}